// round 1
// baseline (speedup 1.0000x reference)
#include <cuda_runtime.h>
#include <stdint.h>

// reference(x) = (U*S)@Vh from SVD of x == exact reconstruction of x.
// So the kernel is a pure D2D copy of N*3*3 floats.

__global__ void __launch_bounds__(256) copy_f4_kernel(const float4* __restrict__ src,
                                                      float4* __restrict__ dst,
                                                      long long n4) {
    long long i = (long long)blockIdx.x * blockDim.x + threadIdx.x;
    long long stride = (long long)gridDim.x * blockDim.x;
    for (; i < n4; i += stride) {
        dst[i] = src[i];
    }
}

__global__ void __launch_bounds__(256) copy_f_tail_kernel(const float* __restrict__ src,
                                                          float* __restrict__ dst,
                                                          long long start, long long n) {
    long long i = start + (long long)blockIdx.x * blockDim.x + threadIdx.x;
    if (i < n) dst[i] = src[i];
}

extern "C" void kernel_launch(void* const* d_in, const int* in_sizes, int n_in,
                              void* d_out, int out_size) {
    const float* x = (const float*)d_in[0];
    float* out = (float*)d_out;
    long long n = (long long)in_sizes[0];   // total float elements (N*3*3)

    long long n4 = n / 4;
    if (n4 > 0) {
        int threads = 256;
        // enough blocks to saturate; grid-stride handles remainder
        long long want = (n4 + threads - 1) / threads;
        int blocks = (int)(want > 148 * 32 ? 148 * 32 : want);
        if (blocks < 1) blocks = 1;
        copy_f4_kernel<<<blocks, threads>>>((const float4*)x, (float4*)out, n4);
    }
    long long tail_start = n4 * 4;
    long long tail = n - tail_start;
    if (tail > 0) {
        copy_f_tail_kernel<<<1, 256>>>(x, out, tail_start, n);
    }
}

// round 2
// speedup vs baseline: 1.1134x; 1.1134x over previous
#include <cuda_runtime.h>
#include <stdint.h>

// reference(x) = (U*S)@Vh from SVD of x == exact SVD reconstruction == x.
// Kernel = pure D2D streaming copy of N*3*3 floats. DRAM-bound.
//
// Strategy: 8 independent float4 loads per thread (MLP=8, 128B/thread),
// block-strided addressing for perfect coalescing, exact-fit grid so the
// hot path has no bounds checks and no loop-carried arithmetic.

#define CP_THREADS 256
#define CP_UNROLL  8

__global__ void __launch_bounds__(CP_THREADS) copy_unroll_kernel(
    const float4* __restrict__ src, float4* __restrict__ dst, long long n4)
{
    long long base = (long long)blockIdx.x * (CP_THREADS * CP_UNROLL) + threadIdx.x;

    if (base + (long long)(CP_UNROLL - 1) * CP_THREADS < n4) {
        float4 v[CP_UNROLL];
#pragma unroll
        for (int u = 0; u < CP_UNROLL; u++)
            v[u] = src[base + (long long)u * CP_THREADS];
#pragma unroll
        for (int u = 0; u < CP_UNROLL; u++)
            dst[base + (long long)u * CP_THREADS] = v[u];
    } else {
#pragma unroll
        for (int u = 0; u < CP_UNROLL; u++) {
            long long i = base + (long long)u * CP_THREADS;
            if (i < n4) dst[i] = src[i];
        }
    }
}

__global__ void __launch_bounds__(256) copy_f_tail_kernel(
    const float* __restrict__ src, float* __restrict__ dst,
    long long start, long long n)
{
    long long i = start + (long long)blockIdx.x * blockDim.x + threadIdx.x;
    if (i < n) dst[i] = src[i];
}

extern "C" void kernel_launch(void* const* d_in, const int* in_sizes, int n_in,
                              void* d_out, int out_size) {
    const float* x = (const float*)d_in[0];
    float* out = (float*)d_out;
    long long n = (long long)in_sizes[0];   // total float elements (N*3*3)

    long long n4 = n / 4;
    if (n4 > 0) {
        long long per_block = (long long)CP_THREADS * CP_UNROLL;
        int blocks = (int)((n4 + per_block - 1) / per_block);
        copy_unroll_kernel<<<blocks, CP_THREADS>>>((const float4*)x, (float4*)out, n4);
    }
    long long tail_start = n4 * 4;
    if (n - tail_start > 0) {
        copy_f_tail_kernel<<<1, 256>>>(x, out, tail_start, n);
    }
}